// round 1
// baseline (speedup 1.0000x reference)
#include <cuda_runtime.h>
#include <math.h>
#include <stdint.h>

// Problem constants (QMixtralSparseMoeBlock): B=2,S=512 -> T=1024, H=1024, F=3584, E=8, top-2
#define T_MAX 1024
#define H_DIM 1024
#define E_NUM 8
#define F_DIM 3584
#define TOPK  2
#define NSLOT (T_MAX * TOPK)   // 2048 (every token picks exactly 2 experts)

// ---------------- scratch (device globals; no allocations allowed) ----------------
__device__ int   g_off[E_NUM];                       // slot offset per expert
__device__ int   g_cnt[E_NUM];                       // slots per expert
__device__ int   g_tok[NSLOT];                       // slot -> token
__device__ float g_wt[NSLOT];                        // slot -> routing weight
__device__ int   g_tok_slot[NSLOT];                  // (token,k) -> slot
__device__ int   g_top_idx[NSLOT];                   // (token,k) -> expert
__device__ float g_top_w[NSLOT];                     // (token,k) -> weight
__device__ float g_h1[(size_t)NSLOT * F_DIM];        // 29.4 MB
__device__ float g_h3[(size_t)NSLOT * F_DIM];        // 29.4 MB
__device__ float g_act[(size_t)NSLOT * F_DIM];       // 29.4 MB
__device__ float g_y[(size_t)NSLOT * H_DIM];         // 8 MB (weighted per-slot outputs)

// ---------------- packed f32x2 FMA (full-rate fp32 on sm_100+) ----------------
__device__ __forceinline__ void ffma2(float2& d, const float2& a, const float2& b, const float2& c) {
#if defined(__CUDA_ARCH__) && (__CUDA_ARCH__ >= 1000)
    asm("fma.rn.f32x2 %0, %1, %2, %3;"
        : "=l"(reinterpret_cast<unsigned long long&>(d))
        : "l"(reinterpret_cast<const unsigned long long&>(a)),
          "l"(reinterpret_cast<const unsigned long long&>(b)),
          "l"(reinterpret_cast<const unsigned long long&>(c)));
#else
    d.x = fmaf(a.x, b.x, c.x);
    d.y = fmaf(a.y, b.y, c.y);
#endif
}

// ---------------- router: logits, top-2, renormalized weights ----------------
__global__ void router_kernel(const float* __restrict__ x, const float* __restrict__ gw,
                              float* __restrict__ logits_out, int write_logits, int nT) {
    int gwarp = (blockIdx.x * blockDim.x + threadIdx.x) >> 5;
    int lane  = threadIdx.x & 31;
    if (gwarp >= nT) return;
    const float* xr = x + (size_t)gwarp * H_DIM;

    float acc[E_NUM];
#pragma unroll
    for (int e = 0; e < E_NUM; e++) acc[e] = 0.f;

    for (int h = lane; h < H_DIM; h += 32) {
        float xv = xr[h];
#pragma unroll
        for (int e = 0; e < E_NUM; e++) acc[e] += xv * gw[e * H_DIM + h];
    }
#pragma unroll
    for (int e = 0; e < E_NUM; e++) {
#pragma unroll
        for (int o = 16; o > 0; o >>= 1) acc[e] += __shfl_xor_sync(0xFFFFFFFFu, acc[e], o);
    }
    if (lane == 0) {
        if (write_logits) {
#pragma unroll
            for (int e = 0; e < E_NUM; e++) logits_out[gwarp * E_NUM + e] = acc[e];
        }
        // top-2 (ties -> lower index, matching jax top_k)
        int i0 = 0;
#pragma unroll
        for (int e = 1; e < E_NUM; e++) if (acc[e] > acc[i0]) i0 = e;
        int i1 = (i0 == 0) ? 1 : 0;
#pragma unroll
        for (int e = 0; e < E_NUM; e++) if (e != i0 && acc[e] > acc[i1]) i1 = e;
        // renormalized softmax weights: p0/(p0+p1) = 1/(1+exp(l1-l0))
        float w0 = 1.f / (1.f + expf(acc[i1] - acc[i0]));
        float w1 = 1.f - w0;
        g_top_idx[2 * gwarp + 0] = i0;
        g_top_idx[2 * gwarp + 1] = i1;
        g_top_w[2 * gwarp + 0] = w0;
        g_top_w[2 * gwarp + 1] = w1;
    }
}

// ---------------- deterministic per-expert slot lists (single block scan) ----------------
__global__ void build_lists_kernel(int nT) {
    int t = threadIdx.x;  // 1024 threads
    __shared__ int sh[T_MAX];
    __shared__ int s_base;

    int e0 = -1, e1 = -1;
    float wv0 = 0.f, wv1 = 0.f;
    if (t < nT) {
        e0 = g_top_idx[2 * t + 0];
        e1 = g_top_idx[2 * t + 1];
        wv0 = g_top_w[2 * t + 0];
        wv1 = g_top_w[2 * t + 1];
    }
    if (t == 0) s_base = 0;
    __syncthreads();

    for (int e = 0; e < E_NUM; e++) {
        if (t == 0) g_off[e] = s_base;
        __syncthreads();
        for (int k = 0; k < TOPK; k++) {
            int sel = ((k == 0 ? e0 : e1) == e) ? 1 : 0;
            sh[t] = sel;
            __syncthreads();
            // Hillis-Steele inclusive scan
            for (int d = 1; d < T_MAX; d <<= 1) {
                int v = (t >= d) ? sh[t - d] : 0;
                __syncthreads();
                sh[t] += v;
                __syncthreads();
            }
            int incl = sh[t];
            int total = sh[T_MAX - 1];
            if (sel) {
                int slot = s_base + incl - 1;
                g_tok[slot] = t;
                g_wt[slot]  = (k == 0 ? wv0 : wv1);
                g_tok_slot[2 * t + k] = slot;
            }
            __syncthreads();
            if (t == 0) s_base += total;
            __syncthreads();
        }
        if (t == 0) g_cnt[e] = s_base - g_off[e];
        __syncthreads();
    }
}

// ---------------- grouped SGEMM 128x128x8, 256 threads, f32x2 micro-kernel ----------------
// MODE 0: C=g_h1 = gather(X) @ w1[e]^T   (N=F, K=H)
// MODE 1: C=g_h3 = gather(X) @ w3[e]^T   (N=F, K=H)
// MODE 2: C=g_y  = wt * (g_act @ w2[e]^T) (N=H, K=F)
template <int MODE>
__global__ __launch_bounds__(256, 2) void expert_gemm(const float* __restrict__ X,
                                                      const float* __restrict__ W) {
    constexpr int N = (MODE == 2) ? H_DIM : F_DIM;
    constexpr int K = (MODE == 2) ? F_DIM : H_DIM;
    constexpr bool GATHER = (MODE != 2);
    constexpr bool SCALE  = (MODE == 2);

    float* C;
    if (MODE == 0) C = g_h1; else if (MODE == 1) C = g_h3; else C = g_y;
    const float* A = (MODE == 2) ? g_act : X;

    const int e   = blockIdx.z;
    const int cnt = g_cnt[e];
    const int off = g_off[e];
    const int m0  = blockIdx.x * 128;
    if (m0 >= cnt) return;
    const int n0  = blockIdx.y * 128;
    const float* Wb = W + (size_t)e * N * K;

    __shared__ float As[8][128];
    __shared__ float Bs[8][128];

    const int tid   = threadIdx.x;
    const int l_row = tid >> 1;           // 0..127
    const int k4    = (tid & 1) * 4;      // 0 or 4

    bool a_valid = (m0 + l_row) < cnt;
    const float* Arow;
    if (GATHER) {
        int tok = a_valid ? g_tok[off + m0 + l_row] : 0;
        Arow = A + (size_t)tok * K;
    } else {
        Arow = A + (size_t)(off + m0 + (a_valid ? l_row : 0)) * K;
    }
    const float* Brow = Wb + (size_t)(n0 + l_row) * K;

    const int tx  = tid & 15;
    const int ty  = tid >> 4;
    const int tx4 = tx * 4;
    const int ty4 = ty * 4;

    float2 acc[8][4];
#pragma unroll
    for (int i = 0; i < 8; i++)
#pragma unroll
        for (int j = 0; j < 4; j++) acc[i][j] = make_float2(0.f, 0.f);

    float4 a_next = a_valid ? *(const float4*)(Arow + k4) : make_float4(0, 0, 0, 0);
    float4 b_next = *(const float4*)(Brow + k4);

    for (int kt = 0; kt < K; kt += 8) {
        __syncthreads();
        As[k4 + 0][l_row] = a_next.x;
        As[k4 + 1][l_row] = a_next.y;
        As[k4 + 2][l_row] = a_next.z;
        As[k4 + 3][l_row] = a_next.w;
        Bs[k4 + 0][l_row] = b_next.x;
        Bs[k4 + 1][l_row] = b_next.y;
        Bs[k4 + 2][l_row] = b_next.z;
        Bs[k4 + 3][l_row] = b_next.w;
        __syncthreads();

        if (kt + 8 < K) {
            a_next = a_valid ? *(const float4*)(Arow + kt + 8 + k4) : make_float4(0, 0, 0, 0);
            b_next = *(const float4*)(Brow + kt + 8 + k4);
        }

#pragma unroll
        for (int k = 0; k < 8; k++) {
            float4 a0 = *(const float4*)&As[k][ty4];
            float4 a1 = *(const float4*)&As[k][64 + ty4];
            float4 b0 = *(const float4*)&Bs[k][tx4];
            float4 b1 = *(const float4*)&Bs[k][64 + tx4];
            float2 bp[4] = {make_float2(b0.x, b0.y), make_float2(b0.z, b0.w),
                            make_float2(b1.x, b1.y), make_float2(b1.z, b1.w)};
            float av[8] = {a0.x, a0.y, a0.z, a0.w, a1.x, a1.y, a1.z, a1.w};
#pragma unroll
            for (int i = 0; i < 8; i++) {
                float2 a2 = make_float2(av[i], av[i]);
#pragma unroll
                for (int j = 0; j < 4; j++) ffma2(acc[i][j], a2, bp[j], acc[i][j]);
            }
        }
    }

    // epilogue
#pragma unroll
    for (int i = 0; i < 8; i++) {
        int mrel = (i < 4) ? (ty4 + i) : (64 + ty4 + i - 4);
        int m = m0 + mrel;
        if (m >= cnt) continue;
        float s = 1.f;
        if (SCALE) s = g_wt[off + m];
        float* crow = C + (size_t)(off + m) * N;
        float4 v0 = make_float4(acc[i][0].x * s, acc[i][0].y * s, acc[i][1].x * s, acc[i][1].y * s);
        float4 v1 = make_float4(acc[i][2].x * s, acc[i][2].y * s, acc[i][3].x * s, acc[i][3].y * s);
        *(float4*)(crow + n0 + tx4)      = v0;
        *(float4*)(crow + n0 + 64 + tx4) = v1;
    }
}

// ---------------- act = silu(h1) * h3 ----------------
__global__ void act_kernel() {
    const size_t n4 = (size_t)NSLOT * F_DIM / 4;
    size_t i = (size_t)blockIdx.x * blockDim.x + threadIdx.x;
    if (i >= n4) return;
    float4 a = ((const float4*)g_h1)[i];
    float4 b = ((const float4*)g_h3)[i];
    float4 r;
    r.x = (a.x / (1.f + expf(-a.x))) * b.x;
    r.y = (a.y / (1.f + expf(-a.y))) * b.y;
    r.z = (a.z / (1.f + expf(-a.z))) * b.z;
    r.w = (a.w / (1.f + expf(-a.w))) * b.w;
    ((float4*)g_act)[i] = r;
}

// ---------------- combine two weighted slots per token ----------------
__global__ void combine_kernel(float* __restrict__ out, int nT) {
    const int HQ = H_DIM / 4;
    int i = blockIdx.x * blockDim.x + threadIdx.x;
    if (i >= nT * HQ) return;
    int t = i / HQ;
    int c = i % HQ;
    int s0 = g_tok_slot[2 * t + 0];
    int s1 = g_tok_slot[2 * t + 1];
    float4 v0 = ((const float4*)g_y)[(size_t)s0 * HQ + c];
    float4 v1 = ((const float4*)g_y)[(size_t)s1 * HQ + c];
    float4 r = make_float4(v0.x + v1.x, v0.y + v1.y, v0.z + v1.z, v0.w + v1.w);
    ((float4*)out)[i] = r;
}

// ---------------- launch ----------------
extern "C" void kernel_launch(void* const* d_in, const int* in_sizes, int n_in,
                              void* d_out, int out_size) {
    const float* x  = (const float*)d_in[0];  // [B,S,H]
    const float* gw = (const float*)d_in[1];  // [E,H]
    const float* w1 = (const float*)d_in[2];  // [E,F,H]
    const float* w2 = (const float*)d_in[3];  // [E,H,F]
    const float* w3 = (const float*)d_in[4];  // [E,F,H]
    float* out = (float*)d_out;

    int nT = in_sizes[0] / H_DIM;             // 1024
    if (nT > T_MAX) nT = T_MAX;

    int write_logits = (out_size >= nT * H_DIM + nT * E_NUM) ? 1 : 0;
    float* logits = out + (size_t)nT * H_DIM;

    // 1) router
    {
        int warps = nT;
        int threads = 256;
        int blocks = (warps * 32 + threads - 1) / threads;
        router_kernel<<<blocks, threads>>>(x, gw, logits, write_logits, nT);
    }
    // 2) expert slot lists (deterministic)
    build_lists_kernel<<<1, T_MAX>>>(nT);

    // 3) FF1: h1 and h3
    {
        dim3 grid((nT + 127) / 128, F_DIM / 128, E_NUM);
        expert_gemm<0><<<grid, 256>>>(x, w1);
        expert_gemm<1><<<grid, 256>>>(x, w3);
    }
    // 4) activation
    {
        size_t n4 = (size_t)NSLOT * F_DIM / 4;
        int threads = 256;
        int blocks = (int)((n4 + threads - 1) / threads);
        act_kernel<<<blocks, threads>>>();
    }
    // 5) FF2 (scaled by routing weight)
    {
        dim3 grid((nT + 127) / 128, H_DIM / 128, E_NUM);
        expert_gemm<2><<<grid, 256>>>(nullptr, w2);
    }
    // 6) combine
    {
        int n = nT * (H_DIM / 4);
        int threads = 256;
        int blocks = (n + threads - 1) / threads;
        combine_kernel<<<blocks, threads>>>(out, nT);
    }
}